// round 13
// baseline (speedup 1.0000x reference)
#include <cuda_runtime.h>
#include <cuda_fp16.h>
#include <cstdint>
#include <math.h>

#define NN 100000
#define CC 128
#define KK 16
#define BB 16
#define MT 128          // nodes per block
#define NTHREADS 256
#define EPSF 1e-9f
#define TSTR 272        // padded row stride (bytes) for sT / W2T 16-row tiles

// ---------------- dynamic shared-memory layout (bytes) ----------------
#define OFF_XH    0        // x_hi fp16 [128][128], 16B-chunk XOR swizzle (32768)
#define OFF_W2TH  32768    // W2^T [16][128] fp16, 272B row stride (4352)
#define OFF_STH   37120    // s^T  [16][128] fp16 (4352)
#define OFF_LS    41472    // s fp32 [128][16]           (8192)
#define OFF_GUM   49664    // gumbel fp32 [128][16]      (8192)
#define OFF_PS    57856    // pos [128][2]               (1024)
#define OFF_BSM   58880    // batch [128] int            (512)
#define OFF_B1    59392    // b1 [128]                   (512)
#define OFF_B2    59904    // 64
#define OFF_ACT   59968    // 64
#define OFF_SC    60032    // 16
#define SMEM_TOTAL 60048

// -------- device scratch --------
__device__ float g_sum_s[KK];
__device__ float g_ent;
__device__ float g_A[KK][2];
__device__ float g_P[KK];
__device__ float g_bs[BB][KK];
__device__ float g_bsp[BB][KK][2];
// W1 (fp16) in mma.sync B-fragment order: [ks=8][j=16][lane=32] x uint2(bh0, bh1)
__device__ __align__(16) uint2 g_W1frag[8 * 16 * 32];

// swizzled byte offset inside a 128x128 fp16 tile, row-major 256B rows,
// 16B chunks XORed with (row & 7)
__host__ __device__ __forceinline__ uint32_t sw_off(int row, int chunk) {
    return (uint32_t)(row * 256 + ((chunk ^ (row & 7)) << 4));
}

// ---------------- PTX helpers ----------------
__device__ __forceinline__ uint32_t smem_u32(const void* p) {
    uint32_t a;
    asm("{ .reg .u64 t; cvta.to.shared.u64 t, %1; cvt.u32.u64 %0, t; }" : "=r"(a) : "l"(p));
    return a;
}
__device__ __forceinline__ void ldmx4(uint32_t* r, uint32_t addr) {
    asm volatile("ldmatrix.sync.aligned.m8n8.x4.shared.b16 {%0,%1,%2,%3}, [%4];"
                 : "=r"(r[0]), "=r"(r[1]), "=r"(r[2]), "=r"(r[3]) : "r"(addr));
}
__device__ __forceinline__ void ldmx2(uint32_t* r, uint32_t addr) {
    asm volatile("ldmatrix.sync.aligned.m8n8.x2.shared.b16 {%0,%1}, [%2];"
                 : "=r"(r[0]), "=r"(r[1]) : "r"(addr));
}
__device__ __forceinline__ void ldmx2t(uint32_t* r, uint32_t addr) {
    asm volatile("ldmatrix.sync.aligned.m8n8.x2.trans.shared.b16 {%0,%1}, [%2];"
                 : "=r"(r[0]), "=r"(r[1]) : "r"(addr));
}
__device__ __forceinline__ void mma_f16(float* d, const uint32_t* a, const uint32_t* b) {
    asm volatile("mma.sync.aligned.m16n8k16.row.col.f32.f16.f16.f32 "
                 "{%0,%1,%2,%3}, {%4,%5,%6,%7}, {%8,%9}, {%0,%1,%2,%3};"
                 : "+f"(d[0]), "+f"(d[1]), "+f"(d[2]), "+f"(d[3])
                 : "r"(a[0]), "r"(a[1]), "r"(a[2]), "r"(a[3]), "r"(b[0]), "r"(b[1]));
}
__device__ __forceinline__ void red_add_v2(float* addr, float a, float b) {
    asm volatile("red.global.add.v2.f32 [%0], {%1, %2};"
                 :: "l"(addr), "f"(a), "f"(b) : "memory");
}

// single-instruction pack: result = (f16(b) << 16) | f16(a)
__device__ __forceinline__ uint32_t pack_f16(float a, float b) {
    uint32_t u;
    asm("cvt.rn.f16x2.f32 %0, %1, %2;" : "=r"(u) : "f"(b), "f"(a));
    return u;
}

// ---------------- init: zero accum + out_pool, build W1 fragment array ----------------
__global__ void init_kernel(float* __restrict__ out_pool, const float* __restrict__ W1) {
    int i = blockIdx.x * blockDim.x + threadIdx.x;
    if (i < BB * KK * CC) out_pool[i] = 0.0f;
    if (i < KK) {
        g_sum_s[i] = 0.f; g_P[i] = 0.f;
        g_A[i][0] = 0.f; g_A[i][1] = 0.f;
    }
    if (i == 0) g_ent = 0.f;
    if (i < BB * KK)     ((float*)g_bs)[i] = 0.f;
    if (i < BB * KK * 2) ((float*)g_bsp)[i] = 0.f;

    if (i < 8 * 16 * 32) {
        const int ks = i >> 9;
        const int j  = (i >> 5) & 15;
        const int t  = i & 31;
        const int n  = j * 8 + (t >> 2);
        const int k0 = ks * 16 + (t & 3) * 2;
        uint2 w;
        w.x = pack_f16(W1[(size_t)(k0 + 0) * CC + n], W1[(size_t)(k0 + 1) * CC + n]);
        w.y = pack_f16(W1[(size_t)(k0 + 8) * CC + n], W1[(size_t)(k0 + 9) * CC + n]);
        g_W1frag[i] = w;
    }
}

// ---------------- fused kernel (3 CTAs/SM target) ----------------
__global__ __launch_bounds__(NTHREADS, 3)
void fused_kernel(const float* __restrict__ x,
                  const float* __restrict__ pos,
                  const int*   __restrict__ batch,
                  const float* __restrict__ gumbel,
                  const float* __restrict__ b1,
                  const float* __restrict__ W2,
                  const float* __restrict__ b2,
                  const float* __restrict__ scaling,
                  const float* __restrict__ active,
                  float* __restrict__ out_pool,
                  float* __restrict__ out_s)
{
    extern __shared__ __align__(16) char smem[];
    const uint32_t sb = smem_u32(smem);
    const int tid = threadIdx.x;
    const int tx  = tid & 31;
    const int wp  = tid >> 5;
    const int n0  = blockIdx.x * MT;
    const int nvalid = min(MT, NN - n0);

    float* Ls  = (float*)(smem + OFF_LS);
    float* gum = (float*)(smem + OFF_GUM);
    float* Ps  = (float*)(smem + OFF_PS);
    int*   Bsm = (int*)(smem + OFF_BSM);
    float* b1s = (float*)(smem + OFF_B1);
    float* b2s = (float*)(smem + OFF_B2);
    float* acts= (float*)(smem + OFF_ACT);
    float* scs = (float*)(smem + OFF_SC);

    // ---- x tile: fp32 -> fp16 into swizzled smem ([m][k]) ----
    {
        const float4* xg = (const float4*)(x + (size_t)n0 * CC);
        for (int i = tid; i < MT * CC / 8; i += NTHREADS) {   // 2048 groups of 8 elems
            const int row   = i >> 4;
            const int chunk = i & 15;
            float4 v0, v1;
            if (row < nvalid) {
                v0 = xg[(size_t)row * 32 + chunk * 2];
                v1 = xg[(size_t)row * 32 + chunk * 2 + 1];
            } else {
                v0 = v1 = make_float4(0.f, 0.f, 0.f, 0.f);
            }
            uint4 hi;
            hi.x = pack_f16(v0.x, v0.y); hi.y = pack_f16(v0.z, v0.w);
            hi.z = pack_f16(v1.x, v1.y); hi.w = pack_f16(v1.z, v1.w);
            *(uint4*)(smem + OFF_XH + sw_off(row, chunk)) = hi;
        }
    }

    // ---- gumbel tile -> smem (coalesced) ----
    {
        const float4* gg = (const float4*)(gumbel + (size_t)n0 * KK);
        const int valid4 = nvalid * (KK / 4);
        for (int i = tid; i < MT * KK / 4; i += NTHREADS)
            ((float4*)gum)[i] = (i < valid4) ? gg[i] : make_float4(0.f, 0.f, 0.f, 0.f);
    }

    // ---- W2^T fp16 tile [16][128], 272B row stride ----
    for (int i = tid; i < CC * KK; i += NTHREADS) {
        const int c = i >> 4, k = i & 15;
        *(__half*)(smem + OFF_W2TH + k * TSTR + c * 2) = __float2half_rn(W2[i]);
    }

    // ---- small tiles ----
    if (tid < CC) b1s[tid] = b1[tid];
    if (tid < KK) { b2s[tid] = b2[tid]; acts[tid] = active[tid]; }
    if (tid == 0) scs[0] = scaling[0];
    for (int i = tid; i < MT; i += NTHREADS) {
        if (i < nvalid) {
            Ps[2*i]   = pos[(size_t)(n0 + i) * 2];
            Ps[2*i+1] = pos[(size_t)(n0 + i) * 2 + 1];
            Bsm[i]    = batch[n0 + i];
        } else {
            Ps[2*i] = 0.f; Ps[2*i+1] = 0.f; Bsm[i] = -1;
        }
    }
    __syncthreads();

    // ---- stages A+B interleaved: group g of stage A produces H n-tiles
    //      g*8..g*8+7 == stage-B k-steps 4g..4g+3; consume hpk immediately
    //      so only fa(32) + hpk(16) + lg(8) are live -> fits 85-reg budget.
    const int q2 = (tx & 3) * 2;
    float lg0[4] = {0.f,0.f,0.f,0.f}, lg1[4] = {0.f,0.f,0.f,0.f};
    {
        const int ar = wp * 16 + (tx & 7) + (tx & 8);
        const uint32_t sxh = sb + OFF_XH;
        const uint2* wf = g_W1frag + tx;
        const int br = tx & 7;
        const int bsel = (tx >> 3) & 1;
        const uint32_t w2th = sb + OFF_W2TH;

        #pragma unroll
        for (int g = 0; g < 2; g++) {
            float fa[8][4];
            #pragma unroll
            for (int j = 0; j < 8; j++) { fa[j][0]=0.f; fa[j][1]=0.f; fa[j][2]=0.f; fa[j][3]=0.f; }
            #pragma unroll
            for (int ks = 0; ks < 8; ks++) {
                const int ac = ks * 2 + (tx >> 4);
                uint32_t ahi[4];
                ldmx4(ahi, sxh + sw_off(ar, ac));
                #pragma unroll
                for (int j = 0; j < 8; j++) {
                    const uint2 w = __ldg(wf + (ks * 16 + g * 8 + j) * 32);
                    uint32_t bh[2];
                    bh[0] = w.x; bh[1] = w.y;
                    mma_f16(fa[j], ahi, bh);
                }
            }
            uint32_t hpk[16];
            #pragma unroll
            for (int j = 0; j < 8; j++) {
                const int jj = g * 8 + j;
                const float bc0 = b1s[jj*8 + q2], bc1 = b1s[jj*8 + q2 + 1];
                hpk[j*2]     = pack_f16(fmaxf(fa[j][0] + bc0, 0.f),
                                        fmaxf(fa[j][1] + bc1, 0.f));
                hpk[j*2 + 1] = pack_f16(fmaxf(fa[j][2] + bc0, 0.f),
                                        fmaxf(fa[j][3] + bc1, 0.f));
            }
            // stage B for k-steps 4g..4g+3
            #pragma unroll
            for (int ks2 = 0; ks2 < 4; ks2++) {
                const int ks = g * 4 + ks2;
                const uint32_t* ah = hpk + 4 * ks2;
                const uint32_t coff = (uint32_t)(ks * 2 + bsel) * 16;
                uint32_t bh[2];
                ldmx2(bh, w2th + br * TSTR + coff);
                mma_f16(lg0, ah, bh);
                ldmx2(bh, w2th + (8 + br) * TSTR + coff);
                mma_f16(lg1, ah, bh);
            }
        }
    }

    // ---- fused bias+mask+scale+gumbel+softmax in registers (quad shuffle) ----
    {
        const int r0v = wp * 16 + (tx >> 2);
        const int r1v = r0v + 8;
        const float sc = scs[0];
        float v0[4] = {lg0[0], lg0[1], lg1[0], lg1[1]};
        float v1[4] = {lg0[2], lg0[3], lg1[2], lg1[3]};
        const int kidx[4] = {q2, q2 + 1, 8 + q2, 9 + q2};
        #pragma unroll
        for (int j = 0; j < 4; j++) {
            const int k = kidx[j];
            const float bb = b2s[k];
            const float mk = acts[k];
            const float a0 = (mk == 0.f) ? -1e9f : (v0[j] + bb) * sc;
            const float a1 = (mk == 0.f) ? -1e9f : (v1[j] + bb) * sc;
            v0[j] = a0 + gum[r0v * KK + k];
            v1[j] = a1 + gum[r1v * KK + k];
        }
        float m0 = fmaxf(fmaxf(v0[0], v0[1]), fmaxf(v0[2], v0[3]));
        float m1 = fmaxf(fmaxf(v1[0], v1[1]), fmaxf(v1[2], v1[3]));
        m0 = fmaxf(m0, __shfl_xor_sync(0xffffffffu, m0, 1));
        m0 = fmaxf(m0, __shfl_xor_sync(0xffffffffu, m0, 2));
        m1 = fmaxf(m1, __shfl_xor_sync(0xffffffffu, m1, 1));
        m1 = fmaxf(m1, __shfl_xor_sync(0xffffffffu, m1, 2));
        float s0 = 0.f, s1 = 0.f;
        #pragma unroll
        for (int j = 0; j < 4; j++) {
            v0[j] = __expf(v0[j] - m0); s0 += v0[j];
            v1[j] = __expf(v1[j] - m1); s1 += v1[j];
        }
        s0 += __shfl_xor_sync(0xffffffffu, s0, 1);
        s0 += __shfl_xor_sync(0xffffffffu, s0, 2);
        s1 += __shfl_xor_sync(0xffffffffu, s1, 1);
        s1 += __shfl_xor_sync(0xffffffffu, s1, 2);
        const float i0 = 1.f / s0, i1 = 1.f / s1;
        const bool ok0 = r0v < nvalid, ok1 = r1v < nvalid;
        #pragma unroll
        for (int j = 0; j < 4; j++) {
            v0[j] = ok0 ? v0[j] * i0 : 0.f;
            v1[j] = ok1 ? v1[j] * i1 : 0.f;
        }
        if (ok0) {
            *(float2*)(out_s + (size_t)(n0 + r0v) * KK + q2)     = make_float2(v0[0], v0[1]);
            *(float2*)(out_s + (size_t)(n0 + r0v) * KK + 8 + q2) = make_float2(v0[2], v0[3]);
        }
        if (ok1) {
            *(float2*)(out_s + (size_t)(n0 + r1v) * KK + q2)     = make_float2(v1[0], v1[1]);
            *(float2*)(out_s + (size_t)(n0 + r1v) * KK + 8 + q2) = make_float2(v1[2], v1[3]);
        }
        *(float2*)(Ls + r0v * KK + q2)     = make_float2(v0[0], v0[1]);
        *(float2*)(Ls + r0v * KK + 8 + q2) = make_float2(v0[2], v0[3]);
        *(float2*)(Ls + r1v * KK + q2)     = make_float2(v1[0], v1[1]);
        *(float2*)(Ls + r1v * KK + 8 + q2) = make_float2(v1[2], v1[3]);
        #pragma unroll
        for (int j = 0; j < 4; j++) {
            const int k = kidx[j];
            *(__half*)(smem + OFF_STH + k * TSTR + r0v * 2) = __float2half_rn(v0[j]);
            *(__half*)(smem + OFF_STH + k * TSTR + r1v * 2) = __float2half_rn(v1[j]);
        }
    }
    __syncthreads();

    // ---- stage C1: statistics ----
    const bool uniform = (nvalid == MT) && (Bsm[0] == Bsm[MT-1]);
    if (uniform) {
        const int k = tid >> 4;
        const int g = tid & 15;
        float gs = 0.f, ge = 0.f, gax = 0.f, gay = 0.f, gp = 0.f;
        #pragma unroll
        for (int j = 0; j < 8; j++) {
            const int n = g*8 + j;
            const float sv = Ls[n*KK + k];
            const float px = Ps[2*n], py = Ps[2*n+1];
            gs  += sv;
            ge  += sv * __logf(sv + EPSF);
            gax += sv * px;
            gay += sv * py;
            gp  += sv * (px*px + py*py);
        }
        #pragma unroll
        for (int off = 8; off > 0; off >>= 1) {
            gs  += __shfl_down_sync(0xffffffffu, gs,  off, 16);
            ge  += __shfl_down_sync(0xffffffffu, ge,  off, 16);
            gax += __shfl_down_sync(0xffffffffu, gax, off, 16);
            gay += __shfl_down_sync(0xffffffffu, gay, off, 16);
            gp  += __shfl_down_sync(0xffffffffu, gp,  off, 16);
        }
        if (g == 0) {
            const int b = Bsm[0];
            atomicAdd(&g_sum_s[k], gs);
            atomicAdd(&g_ent, ge);
            red_add_v2(&g_A[k][0], gax, gay);
            atomicAdd(&g_P[k], gp);
            atomicAdd(&g_bs[b][k], gs);
            red_add_v2(&g_bsp[b][k][0], gax, gay);
        }
    } else if (tid < KK) {
        const int k = tid;
        float gs = 0.f, ge = 0.f, gax = 0.f, gay = 0.f, gp = 0.f;
        int cur = Bsm[0];
        float bs = 0.f, bx = 0.f, by = 0.f;
        for (int n = 0; n < MT; n++) {
            const int bv = Bsm[n];
            if (bv < 0) break;
            if (bv != cur) {
                atomicAdd(&g_bs[cur][k], bs);
                red_add_v2(&g_bsp[cur][k][0], bx, by);
                bs = bx = by = 0.f; cur = bv;
            }
            const float sv = Ls[n*KK + k];
            const float px = Ps[2*n], py = Ps[2*n+1];
            gs  += sv;
            ge  += sv * __logf(sv + EPSF);
            gax += sv * px;
            gay += sv * py;
            gp  += sv * (px*px + py*py);
            bs  += sv; bx += sv * px; by += sv * py;
        }
        if (cur >= 0) {
            atomicAdd(&g_bs[cur][k], bs);
            red_add_v2(&g_bsp[cur][k][0], bx, by);
        }
        atomicAdd(&g_sum_s[k], gs);
        atomicAdd(&g_ent, ge);
        red_add_v2(&g_A[k][0], gax, gay);
        atomicAdd(&g_P[k], gp);
    }

    // ---- stage C2: pooled features ----
    if (uniform) {
        // out[b] += s^T @ x via MMA, single-pass fp16: s_h * x_h
        float p0[4] = {0.f,0.f,0.f,0.f}, p1[4] = {0.f,0.f,0.f,0.f};
        const uint32_t sth = sb + OFF_STH;
        const uint32_t xh = sb + OFF_XH;
        const int arow = tx & 15;
        const int asel = tx >> 4;
        #pragma unroll
        for (int ks = 0; ks < 8; ks++) {
            uint32_t sah[4];
            ldmx4(sah, sth + (uint32_t)arow * TSTR + (uint32_t)(ks * 2 + asel) * 16);
            const int brow = ks * 16 + (tx & 15);
            uint32_t bh[2];
            ldmx2t(bh, xh + sw_off(brow, wp * 2));
            mma_f16(p0, sah, bh);
            ldmx2t(bh, xh + sw_off(brow, wp * 2 + 1));
            mma_f16(p1, sah, bh);
        }
        const int b  = Bsm[0];
        const int kr = tx >> 2;
        float* base0 = out_pool + ((size_t)b * KK + kr) * CC + wp * 16;
        float* base1 = out_pool + ((size_t)b * KK + kr + 8) * CC + wp * 16;
        red_add_v2(base0 + q2,     p0[0], p0[1]);
        red_add_v2(base1 + q2,     p0[2], p0[3]);
        red_add_v2(base0 + 8 + q2, p1[0], p1[1]);
        red_add_v2(base1 + 8 + q2, p1[2], p1[3]);
    } else {
        const int k    = tx & 15;
        const int half = tx >> 4;
        const int cb4  = wp * 4 + half * 2;
        const float4* xg4 = (const float4*)(x + (size_t)n0 * CC);
        float4 A0 = make_float4(0.f,0.f,0.f,0.f);
        float4 A1 = make_float4(0.f,0.f,0.f,0.f);
        int cur = Bsm[0];
        for (int n = 0; n < MT; n++) {
            const int bv = Bsm[n];
            if (bv < 0) break;
            if (bv != cur) {
                float* base = out_pool + ((size_t)cur * KK + k) * CC + cb4 * 4;
                red_add_v2(base+0, A0.x, A0.y);
                red_add_v2(base+2, A0.z, A0.w);
                red_add_v2(base+4, A1.x, A1.y);
                red_add_v2(base+6, A1.z, A1.w);
                A0 = make_float4(0.f,0.f,0.f,0.f);
                A1 = make_float4(0.f,0.f,0.f,0.f);
                cur = bv;
            }
            const float sv = Ls[n*KK + k];
            const float4 x0 = xg4[(size_t)n * 32 + cb4];
            const float4 x1 = xg4[(size_t)n * 32 + cb4 + 1];
            A0.x += sv*x0.x; A0.y += sv*x0.y; A0.z += sv*x0.z; A0.w += sv*x0.w;
            A1.x += sv*x1.x; A1.y += sv*x1.y; A1.z += sv*x1.z; A1.w += sv*x1.w;
        }
        if (cur >= 0) {
            float* base = out_pool + ((size_t)cur * KK + k) * CC + cb4 * 4;
            red_add_v2(base+0, A0.x, A0.y);
            red_add_v2(base+2, A0.z, A0.w);
            red_add_v2(base+4, A1.x, A1.y);
            red_add_v2(base+6, A1.z, A1.w);
        }
    }
}

// -------- finalize --------
__global__ void finalize_kernel(const float* __restrict__ active,
                                float* __restrict__ mu_out,
                                float* __restrict__ losses)
{
    __shared__ float mus[BB][KK][2];
    __shared__ float red[256];
    const int tid = threadIdx.x;
    const int b = tid >> 4, k = tid & 15;

    const float denom = g_bs[b][k] + EPSF;
    const float mx = g_bsp[b][k][0] / denom;
    const float my = g_bsp[b][k][1] / denom;
    mus[b][k][0] = mx; mus[b][k][1] = my;
    mu_out[tid * 2]     = mx;
    mu_out[tid * 2 + 1] = my;
    __syncthreads();

    float rep = 0.f;
    #pragma unroll
    for (int j = 0; j < KK; j++) {
        if (j == k) continue;
        float dx = mus[b][k][0] - mus[b][j][0];
        float dy = mus[b][k][1] - mus[b][j][1];
        rep += 1.f / (dx*dx + dy*dy + 1.f);
    }
    red[tid] = rep;
    __syncthreads();
    for (int st = 128; st > 0; st >>= 1) {
        if (tid < st) red[tid] += red[tid + st];
        __syncthreads();
    }

    if (tid == 0) {
        const float sep = red[0] / ((float)(KK * (KK - 1)) + EPSF);
        const float entropy = -g_ent / (float)NN;
        float div = 0.f, prun = 0.f, spat = 0.f, spar = 0.f;
        for (int kk = 0; kk < KK; kk++) {
            const float avg = g_sum_s[kk] / (float)NN;
            div  += avg * __logf(avg + EPSF);
            const float am = active[kk];
            prun += fabsf(avg * (1.f - am));
            spar += am;
            const float S = g_sum_s[kk] + EPSF;
            const float mgx = g_A[kk][0] / S;
            const float mgy = g_A[kk][1] / S;
            spat += g_P[kk] / S - (mgx*mgx + mgy*mgy);
        }
        losses[0] = entropy;
        losses[1] = div;
        losses[2] = spat / (float)KK;
        losses[3] = prun / (float)KK;
        losses[4] = spar / (float)KK;
        losses[5] = sep;
    }
}

extern "C" void kernel_launch(void* const* d_in, const int* in_sizes, int n_in,
                              void* d_out, int out_size) {
    const float* x       = (const float*)d_in[0];
    const float* pos     = (const float*)d_in[1];
    const int*   batch   = (const int*)  d_in[2];
    const float* gumbel  = (const float*)d_in[3];
    const float* W1      = (const float*)d_in[4];
    const float* b1      = (const float*)d_in[5];
    const float* W2      = (const float*)d_in[6];
    const float* b2      = (const float*)d_in[7];
    const float* scaling = (const float*)d_in[8];
    const float* active  = (const float*)d_in[9];

    float* out = (float*)d_out;
    float* out_pool   = out;
    float* out_s      = out + (size_t)BB*KK*CC;
    float* out_mu     = out_s + (size_t)NN*KK;
    float* out_losses = out_mu + (size_t)BB*KK*2;

    cudaFuncSetAttribute(fused_kernel, cudaFuncAttributeMaxDynamicSharedMemorySize,
                         SMEM_TOTAL);

    init_kernel<<<128, 256>>>(out_pool, W1);
    fused_kernel<<<(NN + MT - 1) / MT, NTHREADS, SMEM_TOTAL>>>(
        x, pos, batch, gumbel, b1, W2, b2, scaling, active, out_pool, out_s);
    finalize_kernel<<<1, 256>>>(active, out_mu, out_losses);
}

// round 14
// speedup vs baseline: 1.0465x; 1.0465x over previous
#include <cuda_runtime.h>
#include <cuda_fp16.h>
#include <cstdint>
#include <math.h>

#define NN 100000
#define CC 128
#define KK 16
#define BB 16
#define MT 128          // nodes per block
#define NTHREADS 256
#define EPSF 1e-9f
#define TSTR 272        // padded row stride (bytes) for sT / W2T 16-row tiles

// ---------------- dynamic shared-memory layout (bytes) ----------------
#define OFF_XH    0        // x_hi fp16 [128][128], 16B-chunk XOR swizzle (32768)
#define OFF_W2TH  32768    // W2^T [16][128] fp16, 272B row stride (4352)
#define OFF_STH   37120    // s^T  [16][128] fp16 (4352)
#define OFF_LS    41472    // s fp32 [128][16]           (8192)
#define OFF_GUM   49664    // gumbel fp32 [128][16]      (8192)
#define OFF_PS    57856    // pos [128][2]               (1024)
#define OFF_BSM   58880    // batch [128] int            (512)
#define OFF_B1    59392    // b1 [128]                   (512)
#define OFF_B2    59904    // 64
#define OFF_ACT   59968    // 64
#define OFF_SC    60032    // 4
#define OFF_ENT   60036    // 4 (block-local entropy accumulator)
#define SMEM_TOTAL 60048

// -------- device scratch --------
__device__ float g_sum_s[KK];
__device__ float g_ent;
__device__ float g_A[KK][2];
__device__ float g_P[KK];
__device__ float g_bs[BB][KK];
__device__ float g_bsp[BB][KK][2];
// W1 (fp16) in mma.sync B-fragment order: [ks=8][j=16][lane=32] x uint2(bh0, bh1)
__device__ __align__(16) uint2 g_W1frag[8 * 16 * 32];

// swizzled byte offset inside a 128x128 fp16 tile, row-major 256B rows,
// 16B chunks XORed with (row & 7)
__host__ __device__ __forceinline__ uint32_t sw_off(int row, int chunk) {
    return (uint32_t)(row * 256 + ((chunk ^ (row & 7)) << 4));
}

// ---------------- PTX helpers ----------------
__device__ __forceinline__ uint32_t smem_u32(const void* p) {
    uint32_t a;
    asm("{ .reg .u64 t; cvta.to.shared.u64 t, %1; cvt.u32.u64 %0, t; }" : "=r"(a) : "l"(p));
    return a;
}
__device__ __forceinline__ void ldmx4(uint32_t* r, uint32_t addr) {
    asm volatile("ldmatrix.sync.aligned.m8n8.x4.shared.b16 {%0,%1,%2,%3}, [%4];"
                 : "=r"(r[0]), "=r"(r[1]), "=r"(r[2]), "=r"(r[3]) : "r"(addr));
}
__device__ __forceinline__ void ldmx2(uint32_t* r, uint32_t addr) {
    asm volatile("ldmatrix.sync.aligned.m8n8.x2.shared.b16 {%0,%1}, [%2];"
                 : "=r"(r[0]), "=r"(r[1]) : "r"(addr));
}
__device__ __forceinline__ void ldmx2t(uint32_t* r, uint32_t addr) {
    asm volatile("ldmatrix.sync.aligned.m8n8.x2.trans.shared.b16 {%0,%1}, [%2];"
                 : "=r"(r[0]), "=r"(r[1]) : "r"(addr));
}
__device__ __forceinline__ void mma_f16(float* d, const uint32_t* a, const uint32_t* b) {
    asm volatile("mma.sync.aligned.m16n8k16.row.col.f32.f16.f16.f32 "
                 "{%0,%1,%2,%3}, {%4,%5,%6,%7}, {%8,%9}, {%0,%1,%2,%3};"
                 : "+f"(d[0]), "+f"(d[1]), "+f"(d[2]), "+f"(d[3])
                 : "r"(a[0]), "r"(a[1]), "r"(a[2]), "r"(a[3]), "r"(b[0]), "r"(b[1]));
}
__device__ __forceinline__ void red_add_v2(float* addr, float a, float b) {
    asm volatile("red.global.add.v2.f32 [%0], {%1, %2};"
                 :: "l"(addr), "f"(a), "f"(b) : "memory");
}

// single-instruction pack: result = (f16(b) << 16) | f16(a)
__device__ __forceinline__ uint32_t pack_f16(float a, float b) {
    uint32_t u;
    asm("cvt.rn.f16x2.f32 %0, %1, %2;" : "=r"(u) : "f"(b), "f"(a));
    return u;
}

// ---------------- init: zero accum + out_pool, build W1 fragment array ----------------
__global__ void init_kernel(float* __restrict__ out_pool, const float* __restrict__ W1) {
    int i = blockIdx.x * blockDim.x + threadIdx.x;
    if (i < BB * KK * CC) out_pool[i] = 0.0f;
    if (i < KK) {
        g_sum_s[i] = 0.f; g_P[i] = 0.f;
        g_A[i][0] = 0.f; g_A[i][1] = 0.f;
    }
    if (i == 0) g_ent = 0.f;
    if (i < BB * KK)     ((float*)g_bs)[i] = 0.f;
    if (i < BB * KK * 2) ((float*)g_bsp)[i] = 0.f;

    if (i < 8 * 16 * 32) {
        const int ks = i >> 9;
        const int j  = (i >> 5) & 15;
        const int t  = i & 31;
        const int n  = j * 8 + (t >> 2);
        const int k0 = ks * 16 + (t & 3) * 2;
        uint2 w;
        w.x = pack_f16(W1[(size_t)(k0 + 0) * CC + n], W1[(size_t)(k0 + 1) * CC + n]);
        w.y = pack_f16(W1[(size_t)(k0 + 8) * CC + n], W1[(size_t)(k0 + 9) * CC + n]);
        g_W1frag[i] = w;
    }
}

// ---------------- fused kernel ----------------
__global__ __launch_bounds__(NTHREADS, 2)
void fused_kernel(const float* __restrict__ x,
                  const float* __restrict__ pos,
                  const int*   __restrict__ batch,
                  const float* __restrict__ gumbel,
                  const float* __restrict__ b1,
                  const float* __restrict__ W2,
                  const float* __restrict__ b2,
                  const float* __restrict__ scaling,
                  const float* __restrict__ active,
                  float* __restrict__ out_pool,
                  float* __restrict__ out_s)
{
    extern __shared__ __align__(16) char smem[];
    const uint32_t sb = smem_u32(smem);
    const int tid = threadIdx.x;
    const int tx  = tid & 31;
    const int wp  = tid >> 5;
    const int n0  = blockIdx.x * MT;
    const int nvalid = min(MT, NN - n0);

    float* Ls  = (float*)(smem + OFF_LS);
    float* gum = (float*)(smem + OFF_GUM);
    float* Ps  = (float*)(smem + OFF_PS);
    int*   Bsm = (int*)(smem + OFF_BSM);
    float* b1s = (float*)(smem + OFF_B1);
    float* b2s = (float*)(smem + OFF_B2);
    float* acts= (float*)(smem + OFF_ACT);
    float* scs = (float*)(smem + OFF_SC);
    float* ents= (float*)(smem + OFF_ENT);

    // ---- x tile: fp32 -> fp16 into swizzled smem ([m][k]) ----
    {
        const float4* xg = (const float4*)(x + (size_t)n0 * CC);
        for (int i = tid; i < MT * CC / 8; i += NTHREADS) {   // 2048 groups of 8 elems
            const int row   = i >> 4;
            const int chunk = i & 15;
            float4 v0, v1;
            if (row < nvalid) {
                v0 = xg[(size_t)row * 32 + chunk * 2];
                v1 = xg[(size_t)row * 32 + chunk * 2 + 1];
            } else {
                v0 = v1 = make_float4(0.f, 0.f, 0.f, 0.f);
            }
            uint4 hi;
            hi.x = pack_f16(v0.x, v0.y); hi.y = pack_f16(v0.z, v0.w);
            hi.z = pack_f16(v1.x, v1.y); hi.w = pack_f16(v1.z, v1.w);
            *(uint4*)(smem + OFF_XH + sw_off(row, chunk)) = hi;
        }
    }

    // ---- gumbel tile -> smem (coalesced) ----
    {
        const float4* gg = (const float4*)(gumbel + (size_t)n0 * KK);
        const int valid4 = nvalid * (KK / 4);
        for (int i = tid; i < MT * KK / 4; i += NTHREADS)
            ((float4*)gum)[i] = (i < valid4) ? gg[i] : make_float4(0.f, 0.f, 0.f, 0.f);
    }

    // ---- W2^T fp16 tile [16][128], 272B row stride ----
    for (int i = tid; i < CC * KK; i += NTHREADS) {
        const int c = i >> 4, k = i & 15;
        *(__half*)(smem + OFF_W2TH + k * TSTR + c * 2) = __float2half_rn(W2[i]);
    }

    // ---- small tiles ----
    if (tid < CC) b1s[tid] = b1[tid];
    if (tid < KK) { b2s[tid] = b2[tid]; acts[tid] = active[tid]; }
    if (tid == 0) { scs[0] = scaling[0]; ents[0] = 0.f; }
    for (int i = tid; i < MT; i += NTHREADS) {
        if (i < nvalid) {
            Ps[2*i]   = pos[(size_t)(n0 + i) * 2];
            Ps[2*i+1] = pos[(size_t)(n0 + i) * 2 + 1];
            Bsm[i]    = batch[n0 + i];
        } else {
            Ps[2*i] = 0.f; Ps[2*i+1] = 0.f; Bsm[i] = -1;
        }
    }
    __syncthreads();

    // ---- stage A: H = relu(x_h @ W1_h + b1) as packed-f16 frags hpk[32] ----
    const int q2 = (tx & 3) * 2;
    uint32_t hpk[32];
    {
        const int ar = wp * 16 + (tx & 7) + (tx & 8);
        const uint32_t sxh = sb + OFF_XH;
        const uint2* wf = g_W1frag + tx;
        #pragma unroll
        for (int g = 0; g < 2; g++) {
            float fa[8][4];
            #pragma unroll
            for (int j = 0; j < 8; j++) { fa[j][0]=0.f; fa[j][1]=0.f; fa[j][2]=0.f; fa[j][3]=0.f; }
            #pragma unroll
            for (int ks = 0; ks < 8; ks++) {
                const int ac = ks * 2 + (tx >> 4);
                uint32_t ahi[4];
                ldmx4(ahi, sxh + sw_off(ar, ac));
                #pragma unroll
                for (int j = 0; j < 8; j++) {
                    const uint2 w = __ldg(wf + (ks * 16 + g * 8 + j) * 32);
                    uint32_t bh[2];
                    bh[0] = w.x; bh[1] = w.y;
                    mma_f16(fa[j], ahi, bh);
                }
            }
            #pragma unroll
            for (int j = 0; j < 8; j++) {
                const int jj = g * 8 + j;
                const float bc0 = b1s[jj*8 + q2], bc1 = b1s[jj*8 + q2 + 1];
                hpk[jj*2]     = pack_f16(fmaxf(fa[j][0] + bc0, 0.f),
                                         fmaxf(fa[j][1] + bc1, 0.f));
                hpk[jj*2 + 1] = pack_f16(fmaxf(fa[j][2] + bc0, 0.f),
                                         fmaxf(fa[j][3] + bc1, 0.f));
            }
        }
    }

    // ---- stage B as MMA: logits = H_h @ W2_h; A-frags ARE hpk[4ks..4ks+3] ----
    float lg0[4] = {0.f,0.f,0.f,0.f}, lg1[4] = {0.f,0.f,0.f,0.f};
    {
        const int br = tx & 7;
        const int bsel = (tx >> 3) & 1;
        const uint32_t w2th = sb + OFF_W2TH;
        #pragma unroll
        for (int ks = 0; ks < 8; ks++) {
            const uint32_t* ah = hpk + 4 * ks;
            const uint32_t coff = (uint32_t)(ks * 2 + bsel) * 16;
            uint32_t bh[2];
            ldmx2(bh, w2th + br * TSTR + coff);
            mma_f16(lg0, ah, bh);
            ldmx2(bh, w2th + (8 + br) * TSTR + coff);
            mma_f16(lg1, ah, bh);
        }
    }

    // ---- fused bias+mask+scale+gumbel+softmax+entropy in registers ----
    {
        const int r0v = wp * 16 + (tx >> 2);
        const int r1v = r0v + 8;
        const float sc = scs[0];
        float v0[4] = {lg0[0], lg0[1], lg1[0], lg1[1]};
        float v1[4] = {lg0[2], lg0[3], lg1[2], lg1[3]};
        const int kidx[4] = {q2, q2 + 1, 8 + q2, 9 + q2};
        #pragma unroll
        for (int j = 0; j < 4; j++) {
            const int k = kidx[j];
            const float bb = b2s[k];
            const float mk = acts[k];
            const float a0 = (mk == 0.f) ? -1e9f : (v0[j] + bb) * sc;
            const float a1 = (mk == 0.f) ? -1e9f : (v1[j] + bb) * sc;
            v0[j] = a0 + gum[r0v * KK + k];
            v1[j] = a1 + gum[r1v * KK + k];
        }
        float m0 = fmaxf(fmaxf(v0[0], v0[1]), fmaxf(v0[2], v0[3]));
        float m1 = fmaxf(fmaxf(v1[0], v1[1]), fmaxf(v1[2], v1[3]));
        m0 = fmaxf(m0, __shfl_xor_sync(0xffffffffu, m0, 1));
        m0 = fmaxf(m0, __shfl_xor_sync(0xffffffffu, m0, 2));
        m1 = fmaxf(m1, __shfl_xor_sync(0xffffffffu, m1, 1));
        m1 = fmaxf(m1, __shfl_xor_sync(0xffffffffu, m1, 2));
        float lm0[4], lm1[4];
        float s0 = 0.f, s1 = 0.f;
        #pragma unroll
        for (int j = 0; j < 4; j++) {
            lm0[j] = v0[j] - m0; v0[j] = __expf(lm0[j]); s0 += v0[j];
            lm1[j] = v1[j] - m1; v1[j] = __expf(lm1[j]); s1 += v1[j];
        }
        s0 += __shfl_xor_sync(0xffffffffu, s0, 1);
        s0 += __shfl_xor_sync(0xffffffffu, s0, 2);
        s1 += __shfl_xor_sync(0xffffffffu, s1, 1);
        s1 += __shfl_xor_sync(0xffffffffu, s1, 2);
        // entropy partials: sum_j v_j * lm_j  (then /S - logS at quad leader)
        float t0 = v0[0]*lm0[0] + v0[1]*lm0[1] + v0[2]*lm0[2] + v0[3]*lm0[3];
        float t1 = v1[0]*lm1[0] + v1[1]*lm1[1] + v1[2]*lm1[2] + v1[3]*lm1[3];
        t0 += __shfl_xor_sync(0xffffffffu, t0, 1);
        t0 += __shfl_xor_sync(0xffffffffu, t0, 2);
        t1 += __shfl_xor_sync(0xffffffffu, t1, 1);
        t1 += __shfl_xor_sync(0xffffffffu, t1, 2);
        const float i0 = 1.f / s0, i1 = 1.f / s1;
        const bool ok0 = r0v < nvalid, ok1 = r1v < nvalid;
        if ((tx & 3) == 0) {
            float e = 0.f;
            if (ok0) e += t0 * i0 - __logf(s0);
            if (ok1) e += t1 * i1 - __logf(s1);
            atomicAdd(ents, e);
        }
        #pragma unroll
        for (int j = 0; j < 4; j++) {
            v0[j] = ok0 ? v0[j] * i0 : 0.f;
            v1[j] = ok1 ? v1[j] * i1 : 0.f;
        }
        if (ok0) {
            *(float2*)(out_s + (size_t)(n0 + r0v) * KK + q2)     = make_float2(v0[0], v0[1]);
            *(float2*)(out_s + (size_t)(n0 + r0v) * KK + 8 + q2) = make_float2(v0[2], v0[3]);
        }
        if (ok1) {
            *(float2*)(out_s + (size_t)(n0 + r1v) * KK + q2)     = make_float2(v1[0], v1[1]);
            *(float2*)(out_s + (size_t)(n0 + r1v) * KK + 8 + q2) = make_float2(v1[2], v1[3]);
        }
        *(float2*)(Ls + r0v * KK + q2)     = make_float2(v0[0], v0[1]);
        *(float2*)(Ls + r0v * KK + 8 + q2) = make_float2(v0[2], v0[3]);
        *(float2*)(Ls + r1v * KK + q2)     = make_float2(v1[0], v1[1]);
        *(float2*)(Ls + r1v * KK + 8 + q2) = make_float2(v1[2], v1[3]);
        #pragma unroll
        for (int j = 0; j < 4; j++) {
            const int k = kidx[j];
            *(__half*)(smem + OFF_STH + k * TSTR + r0v * 2) = __float2half_rn(v0[j]);
            *(__half*)(smem + OFF_STH + k * TSTR + r1v * 2) = __float2half_rn(v1[j]);
        }
    }
    __syncthreads();

    if (tid == 0) atomicAdd(&g_ent, ents[0]);

    // ---- stage C1: statistics (entropy handled above) ----
    const bool uniform = (nvalid == MT) && (Bsm[0] == Bsm[MT-1]);
    if (uniform) {
        const int k = tid >> 4;
        const int g = tid & 15;
        float gs = 0.f, gax = 0.f, gay = 0.f, gp = 0.f;
        #pragma unroll
        for (int j = 0; j < 8; j++) {
            const int n = g*8 + j;
            const float sv = Ls[n*KK + k];
            const float px = Ps[2*n], py = Ps[2*n+1];
            gs  += sv;
            gax += sv * px;
            gay += sv * py;
            gp  += sv * (px*px + py*py);
        }
        #pragma unroll
        for (int off = 8; off > 0; off >>= 1) {
            gs  += __shfl_down_sync(0xffffffffu, gs,  off, 16);
            gax += __shfl_down_sync(0xffffffffu, gax, off, 16);
            gay += __shfl_down_sync(0xffffffffu, gay, off, 16);
            gp  += __shfl_down_sync(0xffffffffu, gp,  off, 16);
        }
        if (g == 0) {
            const int b = Bsm[0];
            atomicAdd(&g_sum_s[k], gs);
            red_add_v2(&g_A[k][0], gax, gay);
            atomicAdd(&g_P[k], gp);
            atomicAdd(&g_bs[b][k], gs);
            red_add_v2(&g_bsp[b][k][0], gax, gay);
        }
    } else if (tid < KK) {
        const int k = tid;
        float gs = 0.f, gax = 0.f, gay = 0.f, gp = 0.f;
        int cur = Bsm[0];
        float bs = 0.f, bx = 0.f, by = 0.f;
        for (int n = 0; n < MT; n++) {
            const int bv = Bsm[n];
            if (bv < 0) break;
            if (bv != cur) {
                atomicAdd(&g_bs[cur][k], bs);
                red_add_v2(&g_bsp[cur][k][0], bx, by);
                bs = bx = by = 0.f; cur = bv;
            }
            const float sv = Ls[n*KK + k];
            const float px = Ps[2*n], py = Ps[2*n+1];
            gs  += sv;
            gax += sv * px;
            gay += sv * py;
            gp  += sv * (px*px + py*py);
            bs  += sv; bx += sv * px; by += sv * py;
        }
        if (cur >= 0) {
            atomicAdd(&g_bs[cur][k], bs);
            red_add_v2(&g_bsp[cur][k][0], bx, by);
        }
        atomicAdd(&g_sum_s[k], gs);
        red_add_v2(&g_A[k][0], gax, gay);
        atomicAdd(&g_P[k], gp);
    }

    // ---- stage C2: pooled features ----
    if (uniform) {
        float p0[4] = {0.f,0.f,0.f,0.f}, p1[4] = {0.f,0.f,0.f,0.f};
        const uint32_t sth = sb + OFF_STH;
        const uint32_t xh = sb + OFF_XH;
        const int arow = tx & 15;
        const int asel = tx >> 4;
        #pragma unroll
        for (int ks = 0; ks < 8; ks++) {
            uint32_t sah[4];
            ldmx4(sah, sth + (uint32_t)arow * TSTR + (uint32_t)(ks * 2 + asel) * 16);
            const int brow = ks * 16 + (tx & 15);
            uint32_t bh[2];
            ldmx2t(bh, xh + sw_off(brow, wp * 2));
            mma_f16(p0, sah, bh);
            ldmx2t(bh, xh + sw_off(brow, wp * 2 + 1));
            mma_f16(p1, sah, bh);
        }
        const int b  = Bsm[0];
        const int kr = tx >> 2;
        float* base0 = out_pool + ((size_t)b * KK + kr) * CC + wp * 16;
        float* base1 = out_pool + ((size_t)b * KK + kr + 8) * CC + wp * 16;
        red_add_v2(base0 + q2,     p0[0], p0[1]);
        red_add_v2(base1 + q2,     p0[2], p0[3]);
        red_add_v2(base0 + 8 + q2, p1[0], p1[1]);
        red_add_v2(base1 + 8 + q2, p1[2], p1[3]);
    } else {
        const int k    = tx & 15;
        const int half = tx >> 4;
        const int cb4  = wp * 4 + half * 2;
        const float4* xg4 = (const float4*)(x + (size_t)n0 * CC);
        float4 A0 = make_float4(0.f,0.f,0.f,0.f);
        float4 A1 = make_float4(0.f,0.f,0.f,0.f);
        int cur = Bsm[0];
        for (int n = 0; n < MT; n++) {
            const int bv = Bsm[n];
            if (bv < 0) break;
            if (bv != cur) {
                float* base = out_pool + ((size_t)cur * KK + k) * CC + cb4 * 4;
                red_add_v2(base+0, A0.x, A0.y);
                red_add_v2(base+2, A0.z, A0.w);
                red_add_v2(base+4, A1.x, A1.y);
                red_add_v2(base+6, A1.z, A1.w);
                A0 = make_float4(0.f,0.f,0.f,0.f);
                A1 = make_float4(0.f,0.f,0.f,0.f);
                cur = bv;
            }
            const float sv = Ls[n*KK + k];
            const float4 x0 = xg4[(size_t)n * 32 + cb4];
            const float4 x1 = xg4[(size_t)n * 32 + cb4 + 1];
            A0.x += sv*x0.x; A0.y += sv*x0.y; A0.z += sv*x0.z; A0.w += sv*x0.w;
            A1.x += sv*x1.x; A1.y += sv*x1.y; A1.z += sv*x1.z; A1.w += sv*x1.w;
        }
        if (cur >= 0) {
            float* base = out_pool + ((size_t)cur * KK + k) * CC + cb4 * 4;
            red_add_v2(base+0, A0.x, A0.y);
            red_add_v2(base+2, A0.z, A0.w);
            red_add_v2(base+4, A1.x, A1.y);
            red_add_v2(base+6, A1.z, A1.w);
        }
    }
}

// -------- finalize --------
__global__ void finalize_kernel(const float* __restrict__ active,
                                float* __restrict__ mu_out,
                                float* __restrict__ losses)
{
    __shared__ float mus[BB][KK][2];
    __shared__ float red[256];
    const int tid = threadIdx.x;
    const int b = tid >> 4, k = tid & 15;

    const float denom = g_bs[b][k] + EPSF;
    const float mx = g_bsp[b][k][0] / denom;
    const float my = g_bsp[b][k][1] / denom;
    mus[b][k][0] = mx; mus[b][k][1] = my;
    mu_out[tid * 2]     = mx;
    mu_out[tid * 2 + 1] = my;
    __syncthreads();

    float rep = 0.f;
    #pragma unroll
    for (int j = 0; j < KK; j++) {
        if (j == k) continue;
        float dx = mus[b][k][0] - mus[b][j][0];
        float dy = mus[b][k][1] - mus[b][j][1];
        rep += 1.f / (dx*dx + dy*dy + 1.f);
    }
    red[tid] = rep;
    __syncthreads();
    for (int st = 128; st > 0; st >>= 1) {
        if (tid < st) red[tid] += red[tid + st];
        __syncthreads();
    }

    if (tid == 0) {
        const float sep = red[0] / ((float)(KK * (KK - 1)) + EPSF);
        const float entropy = -g_ent / (float)NN;
        float div = 0.f, prun = 0.f, spat = 0.f, spar = 0.f;
        for (int kk = 0; kk < KK; kk++) {
            const float avg = g_sum_s[kk] / (float)NN;
            div  += avg * __logf(avg + EPSF);
            const float am = active[kk];
            prun += fabsf(avg * (1.f - am));
            spar += am;
            const float S = g_sum_s[kk] + EPSF;
            const float mgx = g_A[kk][0] / S;
            const float mgy = g_A[kk][1] / S;
            spat += g_P[kk] / S - (mgx*mgx + mgy*mgy);
        }
        losses[0] = entropy;
        losses[1] = div;
        losses[2] = spat / (float)KK;
        losses[3] = prun / (float)KK;
        losses[4] = spar / (float)KK;
        losses[5] = sep;
    }
}

extern "C" void kernel_launch(void* const* d_in, const int* in_sizes, int n_in,
                              void* d_out, int out_size) {
    const float* x       = (const float*)d_in[0];
    const float* pos     = (const float*)d_in[1];
    const int*   batch   = (const int*)  d_in[2];
    const float* gumbel  = (const float*)d_in[3];
    const float* W1      = (const float*)d_in[4];
    const float* b1      = (const float*)d_in[5];
    const float* W2      = (const float*)d_in[6];
    const float* b2      = (const float*)d_in[7];
    const float* scaling = (const float*)d_in[8];
    const float* active  = (const float*)d_in[9];

    float* out = (float*)d_out;
    float* out_pool   = out;
    float* out_s      = out + (size_t)BB*KK*CC;
    float* out_mu     = out_s + (size_t)NN*KK;
    float* out_losses = out_mu + (size_t)BB*KK*2;

    cudaFuncSetAttribute(fused_kernel, cudaFuncAttributeMaxDynamicSharedMemorySize,
                         SMEM_TOTAL);

    init_kernel<<<128, 256>>>(out_pool, W1);
    fused_kernel<<<(NN + MT - 1) / MT, NTHREADS, SMEM_TOTAL>>>(
        x, pos, batch, gumbel, b1, W2, b2, scaling, active, out_pool, out_s);
    finalize_kernel<<<1, 256>>>(active, out_mu, out_losses);
}